// round 2
// baseline (speedup 1.0000x reference)
#include <cuda_runtime.h>

// Problem constants
#define TT    4096
#define FF    9
#define NSEQ  2048      // 256*8
#define L1    2049      // pooled len after stage 1
#define L2    1025      // pooled len after stage 2
#define L3    513       // pooled len after stage 3

// Tiling
#define V3      62              // stage-3 pooled outputs per tile
#define NTILES  9               // ceil(513/62)
#define IN_LEN  (8*V3+14)       // 510 input samples needed per tile
#define IN_STR  516             // padded row stride (even, low-conflict)
#define S1_STR  264             // stage1 pooled buffer stride
#define S2_STR  132             // stage2 pooled buffer stride
#define WD1_STR 27              // dup-weight row strides in float2 units
#define WD2_STR 49
#define WD3_STR 97

// SMEM float layout offsets (all even -> float2 aligned)
#define OFF_H0   0
#define OFF_S1   (OFF_H0 + 9*IN_STR)          // 4644
#define OFF_S2   (OFF_S1 + 16*S1_STR)         // 8868
#define OFF_WD1  (OFF_S2 + 32*S2_STR)         // 13092
#define OFF_WD2  (OFF_WD1 + 2*16*WD1_STR)     // +864
#define OFF_WD3  (OFF_WD2 + 2*32*WD2_STR)     // +3136
#define OFF_SB   (OFF_WD3 + 2*16*WD3_STR)     // +3104
#define OFF_FACC (OFF_SB + 64)
#define SM_FLOATS (OFF_FACC + 256)
#define SMEM_BYTES (SM_FLOATS * 4)

typedef unsigned long long u64;

__device__ __forceinline__ u64 ffma2(u64 a, u64 b, u64 c) {
    u64 d;
    asm("fma.rn.f32x2 %0, %1, %2, %3;" : "=l"(d) : "l"(a), "l"(b), "l"(c));
    return d;
}

union F2 { u64 u; float2 f; };

__device__ float g_feat[NSEQ * 16];

__global__ __launch_bounds__(256) void cnn_main(
    const float* __restrict__ x,
    const float* __restrict__ w1, const float* __restrict__ b1,
    const float* __restrict__ w2, const float* __restrict__ b2,
    const float* __restrict__ w3, const float* __restrict__ b3)
{
    extern __shared__ float sm[];
    float*  h0   = sm + OFF_H0;               // [9][IN_STR]
    float*  s1   = sm + OFF_S1;               // [16][S1_STR]
    float*  s2   = sm + OFF_S2;               // [32][S2_STR]
    float2* wd1  = (float2*)(sm + OFF_WD1);   // [16][WD1_STR] dup (w,w)
    float2* wd2  = (float2*)(sm + OFF_WD2);   // [32][WD2_STR]
    float2* wd3  = (float2*)(sm + OFF_WD3);   // [16][WD3_STR]
    float*  sb   = sm + OFF_SB;               // b1[0:16) b2[16:48) b3[48:64)
    float*  facc = sm + OFF_FACC;             // [256]

    const int tid = threadIdx.x;
    const int n   = blockIdx.x;
    const float* xin = x + (size_t)n * (TT * FF);

    // Zero all smem once: provides zero padding everywhere, forever.
    for (int i = tid; i < SM_FLOATS; i += 256) sm[i] = 0.f;
    __syncthreads();

    // Load weights duplicated as (w,w) float2 pairs, biases.
    for (int i = tid; i < 16*27; i += 256) {
        float v = w1[i]; wd1[(i/27)*WD1_STR + (i%27)] = make_float2(v, v);
    }
    for (int i = tid; i < 32*48; i += 256) {
        float v = w2[i]; wd2[(i/48)*WD2_STR + (i%48)] = make_float2(v, v);
    }
    for (int i = tid; i < 16*96; i += 256) {
        float v = w3[i]; wd3[(i/96)*WD3_STR + (i%96)] = make_float2(v, v);
    }
    if (tid < 16)      sb[tid] = b1[tid];
    else if (tid < 48) sb[tid] = b2[tid-16];
    else if (tid < 64) sb[tid] = b3[tid-48];
    __syncthreads();

    for (int tile = 0; tile < NTILES; ++tile) {
        const int va  = tile * V3;
        const int vb  = min(va + V3, L3);
        const int t0  = 8*va - 14;    // global t of h0 local index 0
        const int u1b = 4*va - 6;     // global stage1-pooled idx of s1 local 0
        const int u2b = 2*va - 2;     // global stage2-pooled idx of s2 local 0

        // ---- Phase A: coalesced load + transpose of input tile ----
        for (int idx = tid; idx < IN_LEN*FF; idx += 256) {
            int tl = idx / FF;
            int ci = idx - tl*FF;
            int t  = t0 + tl;
            float v = 0.f;
            if (t >= 0 && t < TT) v = xin[t*FF + ci];
            h0[ci*IN_STR + tl] = v;
        }
        __syncthreads();

        // ---- Phase B: stage1 conv(9->16,k3,p2) + relu + pool2 ----
        #pragma unroll
        for (int it = 0; it < 2; ++it) {
            int item = tid + it*256;
            int cog = item & 7;
            int ug  = item >> 3;            // 0..63
            int co0 = cog * 2;
            int ul0 = ug * 4;
            F2 accA[4], accB[4];
            #pragma unroll
            for (int q = 0; q < 4; ++q) { accA[q].u = 0ULL; accB[q].u = 0ULL; }
            const float2* wpa = wd1 + co0*WD1_STR;
            const float2* wpb = wpa + WD1_STR;
            const float*  hp  = h0 + 2*ul0;
            #pragma unroll
            for (int ci = 0; ci < 9; ++ci) {
                F2 P[5], S[4];
                #pragma unroll
                for (int j = 0; j < 5; ++j) P[j].f = *(const float2*)(hp + 2*j);
                #pragma unroll
                for (int j = 0; j < 4; ++j) { S[j].f.x = P[j].f.y; S[j].f.y = P[j+1].f.x; }
                F2 A0, A1, A2, B0, B1, B2;
                A0.f = wpa[0]; A1.f = wpa[1]; A2.f = wpa[2];
                B0.f = wpb[0]; B1.f = wpb[1]; B2.f = wpb[2];
                #pragma unroll
                for (int q = 0; q < 4; ++q) {
                    accA[q].u = ffma2(A0.u, P[q].u,   accA[q].u);
                    accA[q].u = ffma2(A1.u, S[q].u,   accA[q].u);
                    accA[q].u = ffma2(A2.u, P[q+1].u, accA[q].u);
                    accB[q].u = ffma2(B0.u, P[q].u,   accB[q].u);
                    accB[q].u = ffma2(B1.u, S[q].u,   accB[q].u);
                    accB[q].u = ffma2(B2.u, P[q+1].u, accB[q].u);
                }
                wpa += 3; wpb += 3; hp += IN_STR;
            }
            float ba = sb[co0], bb = sb[co0+1];
            #pragma unroll
            for (int q = 0; q < 4; ++q) {
                int ul  = ul0 + q;
                int ug1 = u1b + ul;
                bool valid = (ug1 >= 0) && (ug1 < L1);
                float v0 = fmaxf(fmaxf(accA[q].f.x, accA[q].f.y) + ba, 0.f);
                float v1 = fmaxf(fmaxf(accB[q].f.x, accB[q].f.y) + bb, 0.f);
                s1[ co0   *S1_STR + ul] = valid ? v0 : 0.f;
                s1[(co0+1)*S1_STR + ul] = valid ? v1 : 0.f;
            }
        }
        __syncthreads();

        // ---- Phase C: stage2 conv(16->32,k3,p2) + relu + pool2 ----
        #pragma unroll
        for (int it = 0; it < 2; ++it) {
            int item = tid + it*256;
            int cog = item & 15;
            int ug  = item >> 4;            // 0..31
            int co0 = cog * 2;
            int ul0 = ug * 4;
            F2 accA[4], accB[4];
            #pragma unroll
            for (int q = 0; q < 4; ++q) { accA[q].u = 0ULL; accB[q].u = 0ULL; }
            const float2* wpa = wd2 + co0*WD2_STR;
            const float2* wpb = wpa + WD2_STR;
            const float*  hp  = s1 + 2*ul0;
            #pragma unroll 4
            for (int ci = 0; ci < 16; ++ci) {
                F2 P[5], S[4];
                #pragma unroll
                for (int j = 0; j < 5; ++j) P[j].f = *(const float2*)(hp + 2*j);
                #pragma unroll
                for (int j = 0; j < 4; ++j) { S[j].f.x = P[j].f.y; S[j].f.y = P[j+1].f.x; }
                F2 A0, A1, A2, B0, B1, B2;
                A0.f = wpa[0]; A1.f = wpa[1]; A2.f = wpa[2];
                B0.f = wpb[0]; B1.f = wpb[1]; B2.f = wpb[2];
                #pragma unroll
                for (int q = 0; q < 4; ++q) {
                    accA[q].u = ffma2(A0.u, P[q].u,   accA[q].u);
                    accA[q].u = ffma2(A1.u, S[q].u,   accA[q].u);
                    accA[q].u = ffma2(A2.u, P[q+1].u, accA[q].u);
                    accB[q].u = ffma2(B0.u, P[q].u,   accB[q].u);
                    accB[q].u = ffma2(B1.u, S[q].u,   accB[q].u);
                    accB[q].u = ffma2(B2.u, P[q+1].u, accB[q].u);
                }
                wpa += 3; wpb += 3; hp += S1_STR;
            }
            float ba = sb[16+co0], bb = sb[16+co0+1];
            #pragma unroll
            for (int q = 0; q < 4; ++q) {
                int ul  = ul0 + q;
                int ug2 = u2b + ul;
                bool valid = (ug2 >= 0) && (ug2 < L2);
                float v0 = fmaxf(fmaxf(accA[q].f.x, accA[q].f.y) + ba, 0.f);
                float v1 = fmaxf(fmaxf(accB[q].f.x, accB[q].f.y) + bb, 0.f);
                s2[ co0   *S2_STR + ul] = valid ? v0 : 0.f;
                s2[(co0+1)*S2_STR + ul] = valid ? v1 : 0.f;
            }
        }
        __syncthreads();

        // ---- Phase D: stage3 conv(32->16,k3,p2) + relu + pool2 + mean-acc ----
        {
            int co  = tid & 15;
            int ug  = tid >> 4;             // 0..15
            int ul0 = ug * 4;
            F2 acc[4];
            #pragma unroll
            for (int q = 0; q < 4; ++q) acc[q].u = 0ULL;
            const float2* wp = wd3 + co*WD3_STR;
            const float*  hp = s2 + 2*ul0;
            #pragma unroll 4
            for (int ci = 0; ci < 32; ++ci) {
                F2 P[5], S[4];
                #pragma unroll
                for (int j = 0; j < 5; ++j) P[j].f = *(const float2*)(hp + 2*j);
                #pragma unroll
                for (int j = 0; j < 4; ++j) { S[j].f.x = P[j].f.y; S[j].f.y = P[j+1].f.x; }
                F2 W0, W1, W2;
                W0.f = wp[0]; W1.f = wp[1]; W2.f = wp[2];
                #pragma unroll
                for (int q = 0; q < 4; ++q) {
                    acc[q].u = ffma2(W0.u, P[q].u,   acc[q].u);
                    acc[q].u = ffma2(W1.u, S[q].u,   acc[q].u);
                    acc[q].u = ffma2(W2.u, P[q+1].u, acc[q].u);
                }
                wp += 3; hp += S2_STR;
            }
            float b = sb[48+co];
            float sum = 0.f;
            #pragma unroll
            for (int q = 0; q < 4; ++q) {
                int v = va + ul0 + q;
                if (v < vb) {
                    float y = fmaxf(fmaxf(acc[q].f.x, acc[q].f.y) + b, 0.f);
                    sum += y;
                }
            }
            facc[tid] += sum;   // fixed slot per thread: deterministic
        }
        __syncthreads();
    }

    // ---- mean over L3=513 positions ----
    if (tid < 16) {
        float s = 0.f;
        #pragma unroll
        for (int u = 0; u < 16; ++u) s += facc[tid + 16*u];
        g_feat[n*16 + tid] = s * (1.0f / 513.0f);
    }
}

// Final: feat [B, J*16=128] -> maxpool k=3 -> [B, 42]
__global__ void final_pool(float* __restrict__ out)
{
    int i = blockIdx.x * blockDim.x + threadIdx.x;
    if (i >= 256*42) return;
    int b = i / 42;
    int g = i - b*42;
    float m = -1e30f;
    #pragma unroll
    for (int e3 = 0; e3 < 3; ++e3) {
        int e = 3*g + e3;
        int j = e >> 4;
        int c = e & 15;
        m = fmaxf(m, g_feat[(b*8 + j)*16 + c]);
    }
    out[i] = m;
}

extern "C" void kernel_launch(void* const* d_in, const int* in_sizes, int n_in,
                              void* d_out, int out_size)
{
    (void)in_sizes; (void)n_in; (void)out_size;
    const float* x  = (const float*)d_in[0];
    const float* w1 = (const float*)d_in[1];
    const float* b1 = (const float*)d_in[2];
    const float* w2 = (const float*)d_in[3];
    const float* b2 = (const float*)d_in[4];
    const float* w3 = (const float*)d_in[5];
    const float* b3 = (const float*)d_in[6];
    float* out = (float*)d_out;

    cudaFuncSetAttribute(cnn_main, cudaFuncAttributeMaxDynamicSharedMemorySize, SMEM_BYTES);
    cnn_main<<<NSEQ, 256, SMEM_BYTES>>>(x, w1, b1, w2, b2, w3, b3);
    final_pool<<<42, 256>>>(out);
}

// round 3
// speedup vs baseline: 1.1417x; 1.1417x over previous
#include <cuda_runtime.h>

typedef unsigned long long u64;

// Problem constants
#define TT    4096
#define FF    9
#define NSEQ  2048
#define L1    2049
#define L2    1025
#define L3    513

// Tiling
#define V3      40
#define NTILES  13              // 12*40=480, last tile 33
#define IN_LEN  (8*V3+14)       // 334

// Row strides in u64 (pair) units
#define P0   339                // h0 dup rows, reads <=337
#define P1   173                // s1 dup rows, writes <=167, reads <=169
#define P2   85                 // s2 dup rows, writes <=83, reads <=81
#define W1S  29                 // weight pair-row strides (odd -> conflict-free)
#define W2S  49
#define W3S  97

// SMEM float offsets (all even -> 8B aligned)
#define OFF_H0   0
#define OFF_S1   (OFF_H0 + 9*2*P0)      // 6102
#define OFF_S2   (OFF_S1 + 16*2*P1)     // +5536
#define OFF_W1   (OFF_S2 + 32*2*P2)     // +5440
#define OFF_W2   (OFF_W1 + 8*2*W1S)     // +464
#define OFF_W3   (OFF_W2 + 16*2*W2S)    // +1568
#define OFF_SB   (OFF_W3 + 8*2*W3S)     // +1552
#define OFF_FACC (OFF_SB + 64)
#define SM_FLOATS (OFF_FACC + 2*320)    // 21366
#define SMEM_BYTES (SM_FLOATS * 4)

__device__ __forceinline__ u64 ffma2(u64 a, u64 b, u64 c) {
    u64 d;
    asm("fma.rn.f32x2 %0, %1, %2, %3;" : "=l"(d) : "l"(a), "l"(b), "l"(c));
    return d;
}
__device__ __forceinline__ u64 pack2(float lo, float hi) {
    u64 v;
    asm("mov.b64 %0, {%1, %2};" : "=l"(v) : "f"(lo), "f"(hi));
    return v;
}
__device__ __forceinline__ void unpack2(u64 v, float& lo, float& hi) {
    asm("mov.b64 {%0, %1}, %2;" : "=f"(lo), "=f"(hi) : "l"(v));
}

__device__ float g_feat[NSEQ * 16];

__global__ __launch_bounds__(256) void cnn_main(
    const float* __restrict__ x,
    const float* __restrict__ w1, const float* __restrict__ b1,
    const float* __restrict__ w2, const float* __restrict__ b2,
    const float* __restrict__ w3, const float* __restrict__ b3)
{
    extern __shared__ float sm[];
    u64* h0p = (u64*)(sm + OFF_H0);     // [9][P0]   dup (x,x)
    u64* s1p = (u64*)(sm + OFF_S1);     // [16][P1]  dup (v,v)
    u64* s2p = (u64*)(sm + OFF_S2);     // [32][P2]  dup (v,v)
    u64* w1p = (u64*)(sm + OFF_W1);     // [8][W1S]  (w_co0, w_co1)
    u64* w2p = (u64*)(sm + OFF_W2);     // [16][W2S]
    u64* w3p = (u64*)(sm + OFF_W3);     // [8][W3S]
    float* sb   = sm + OFF_SB;          // b1[0:16) b2[16:48) b3[48:64)
    u64*  faccp = (u64*)(sm + OFF_FACC);// [320] per-item (ch0,ch1) partial sums

    const int tid = threadIdx.x;
    const int n   = blockIdx.x;
    const float* xin = x + (size_t)n * (TT * FF);

    // Zero all smem once (provides persistent zero padding)
    for (int i = tid; i < SM_FLOATS; i += 256) sm[i] = 0.f;
    __syncthreads();

    // Weights: channel-pair interleaved. w*[co][ci][k] -> pair row co>>1, comp co&1
    for (int i = tid; i < 16*27; i += 256) {
        int co = i / 27, r = i - co*27;
        sm[OFF_W1 + ((co>>1)*W1S + r)*2 + (co&1)] = w1[i];
    }
    for (int i = tid; i < 32*48; i += 256) {
        int co = i / 48, r = i - co*48;
        sm[OFF_W2 + ((co>>1)*W2S + r)*2 + (co&1)] = w2[i];
    }
    for (int i = tid; i < 16*96; i += 256) {
        int co = i / 96, r = i - co*96;
        sm[OFF_W3 + ((co>>1)*W3S + r)*2 + (co&1)] = w3[i];
    }
    if (tid < 16)      sb[tid] = b1[tid];
    else if (tid < 48) sb[tid] = b2[tid-16];
    else if (tid < 64) sb[tid] = b3[tid-48];
    __syncthreads();

    for (int tile = 0; tile < NTILES; ++tile) {
        const int va  = tile * V3;
        const int t0  = 8*va - 14;
        const int u1b = 4*va - 6;
        const int u2b = 2*va - 2;

        // ---- Phase A: coalesced load + transpose + duplicate ----
        for (int idx = tid; idx < IN_LEN*FF; idx += 256) {
            int tl = idx / FF;
            int ci = idx - tl*FF;
            int t  = t0 + tl;
            float v = 0.f;
            if (t >= 0 && t < TT) v = xin[t*FF + ci];
            h0p[ci*P0 + tl] = pack2(v, v);
        }
        __syncthreads();

        // ---- Phase B: stage1 conv(9->16) + relu + pool2 ----
        // item: pair(8) low bits, quad(42) high -> 336 items
        for (int it = 0; it < 2; ++it) {
            int item = tid + it*256;
            if (item >= 336) break;
            int pr  = item & 7;
            int q   = item >> 3;        // 0..41
            int ul0 = q * 4;
            u64 acc[8];
            #pragma unroll
            for (int p = 0; p < 8; ++p) acc[p] = 0ULL;
            const u64* wp = w1p + pr*W1S;
            const u64* hp = h0p + 8*q;
            #pragma unroll 3
            for (int ci = 0; ci < 9; ++ci) {
                u64 P[10];
                #pragma unroll
                for (int j = 0; j < 10; ++j) P[j] = hp[j];
                u64 W0 = wp[0], W1 = wp[1], W2 = wp[2];
                #pragma unroll
                for (int p = 0; p < 8; ++p) {
                    acc[p] = ffma2(W0, P[p],   acc[p]);
                    acc[p] = ffma2(W1, P[p+1], acc[p]);
                    acc[p] = ffma2(W2, P[p+2], acc[p]);
                }
                wp += 3; hp += P0;
            }
            float b0 = sb[2*pr], b1v = sb[2*pr+1];
            u64* r0 = s1p + (2*pr)*P1;
            u64* r1 = r0 + P1;
            #pragma unroll
            for (int q4 = 0; q4 < 4; ++q4) {
                float a0, a1, c0, c1;
                unpack2(acc[2*q4],   a0, a1);
                unpack2(acc[2*q4+1], c0, c1);
                int ul  = ul0 + q4;
                int ug1 = u1b + ul;
                bool valid = (ug1 >= 0) && (ug1 < L1);
                float v0 = fmaxf(fmaxf(a0, c0) + b0, 0.f);
                float v1 = fmaxf(fmaxf(a1, c1) + b1v, 0.f);
                if (!valid) { v0 = 0.f; v1 = 0.f; }
                r0[ul] = pack2(v0, v0);
                r1[ul] = pack2(v1, v1);
            }
        }
        __syncthreads();

        // ---- Phase C: stage2 conv(16->32) + relu + pool2 ----
        // item: pair(16) low, quad(21) high -> 336 items
        for (int it = 0; it < 2; ++it) {
            int item = tid + it*256;
            if (item >= 336) break;
            int pr  = item & 15;
            int q   = item >> 4;        // 0..20
            int ul0 = q * 4;
            u64 acc[8];
            #pragma unroll
            for (int p = 0; p < 8; ++p) acc[p] = 0ULL;
            const u64* wp = w2p + pr*W2S;
            const u64* hp = s1p + 8*q;
            #pragma unroll 2
            for (int ci = 0; ci < 16; ++ci) {
                u64 P[10];
                #pragma unroll
                for (int j = 0; j < 10; ++j) P[j] = hp[j];
                u64 W0 = wp[0], W1 = wp[1], W2 = wp[2];
                #pragma unroll
                for (int p = 0; p < 8; ++p) {
                    acc[p] = ffma2(W0, P[p],   acc[p]);
                    acc[p] = ffma2(W1, P[p+1], acc[p]);
                    acc[p] = ffma2(W2, P[p+2], acc[p]);
                }
                wp += 3; hp += P1;
            }
            float b0 = sb[16 + 2*pr], b1v = sb[16 + 2*pr + 1];
            u64* r0 = s2p + (2*pr)*P2;
            u64* r1 = r0 + P2;
            #pragma unroll
            for (int q4 = 0; q4 < 4; ++q4) {
                float a0, a1, c0, c1;
                unpack2(acc[2*q4],   a0, a1);
                unpack2(acc[2*q4+1], c0, c1);
                int ul  = ul0 + q4;
                int ug2 = u2b + ul;
                bool valid = (ug2 >= 0) && (ug2 < L2);
                float v0 = fmaxf(fmaxf(a0, c0) + b0, 0.f);
                float v1 = fmaxf(fmaxf(a1, c1) + b1v, 0.f);
                if (!valid) { v0 = 0.f; v1 = 0.f; }
                r0[ul] = pack2(v0, v0);
                r1[ul] = pack2(v1, v1);
            }
        }
        __syncthreads();

        // ---- Phase D: stage3 conv(32->16) + relu + pool2 + mean-acc ----
        // item: pair(8) low, pooled pos v(40) high -> 320 items
        for (int it = 0; it < 2; ++it) {
            int item = tid + it*256;
            if (item >= 320) break;
            int pr = item & 7;
            int v  = item >> 3;         // 0..39
            u64 a0 = 0ULL, a1 = 0ULL;
            const u64* wp = w3p + pr*W3S;
            const u64* hp = s2p + 2*v;
            #pragma unroll 4
            for (int ci = 0; ci < 32; ++ci) {
                u64 Q0 = hp[0], Q1 = hp[1], Q2 = hp[2], Q3 = hp[3];
                u64 W0 = wp[0], W1 = wp[1], W2 = wp[2];
                a0 = ffma2(W0, Q0, a0);
                a0 = ffma2(W1, Q1, a0);
                a0 = ffma2(W2, Q2, a0);
                a1 = ffma2(W0, Q1, a1);
                a1 = ffma2(W1, Q2, a1);
                a1 = ffma2(W2, Q3, a1);
                wp += 3; hp += P2;
            }
            float x0, x1, y0, y1;
            unpack2(a0, x0, x1);
            unpack2(a1, y0, y1);
            float b0 = sb[48 + 2*pr], b1v = sb[48 + 2*pr + 1];
            float r0 = fmaxf(fmaxf(x0, y0) + b0, 0.f);
            float r1 = fmaxf(fmaxf(x1, y1) + b1v, 0.f);
            if (va + v < L3) {
                float s0, s1v;
                unpack2(faccp[item], s0, s1v);
                faccp[item] = pack2(s0 + r0, s1v + r1);
            }
        }
        __syncthreads();
    }

    // ---- mean over L3=513 positions ----
    if (tid < 16) {
        int pr = tid >> 1, comp = tid & 1;
        float s = 0.f;
        #pragma unroll
        for (int k = 0; k < 40; ++k)
            s += sm[OFF_FACC + (pr + 8*k)*2 + comp];
        g_feat[n*16 + tid] = s * (1.0f / 513.0f);
    }
}

// Final: feat [B, J*16=128] -> maxpool k=3 -> [B, 42]
__global__ void final_pool(float* __restrict__ out)
{
    int i = blockIdx.x * blockDim.x + threadIdx.x;
    if (i >= 256*42) return;
    int b = i / 42;
    int g = i - b*42;
    float m = -1e30f;
    #pragma unroll
    for (int e3 = 0; e3 < 3; ++e3) {
        int e = 3*g + e3;
        int j = e >> 4;
        int c = e & 15;
        m = fmaxf(m, g_feat[(b*8 + j)*16 + c]);
    }
    out[i] = m;
}

extern "C" void kernel_launch(void* const* d_in, const int* in_sizes, int n_in,
                              void* d_out, int out_size)
{
    (void)in_sizes; (void)n_in; (void)out_size;
    const float* x  = (const float*)d_in[0];
    const float* w1 = (const float*)d_in[1];
    const float* b1 = (const float*)d_in[2];
    const float* w2 = (const float*)d_in[3];
    const float* b2 = (const float*)d_in[4];
    const float* w3 = (const float*)d_in[5];
    const float* b3 = (const float*)d_in[6];
    float* out = (float*)d_out;

    cudaFuncSetAttribute(cnn_main, cudaFuncAttributeMaxDynamicSharedMemorySize, SMEM_BYTES);
    cnn_main<<<NSEQ, 256, SMEM_BYTES>>>(x, w1, b1, w2, b2, w3, b3);
    final_pool<<<42, 256>>>(out);
}